// round 16
// baseline (speedup 1.0000x reference)
#include <cuda_runtime.h>

typedef unsigned long long ull;

#define WIDTH     16384
#define WOUT      16353      // WIDTH - 32 + 1
#define NROWS     1024       // B*H = 16*64
#define FILTER_L  32
#define LUTQ_N    128        // 8 octaves x 16 cells, indexed by bits of v=1+s
#define TILE      1024
#define THREADS   128
#define RPT       8          // outputs per thread (TILE/THREADS)
#define SG_N      1056       // TILE + 31 halo, rounded to multiple of 16
#define NGROUPS   (SG_N/4)   // 264 float4-groups
#define OUT_SCALE 0.17782794100389226f  // sqrt(10^(-15/10))

// Entry i (i = 16*E + m4) covers v in [2^E*(1+m4/16), 2^E*(1+(m4+1)/16)),
// quadratic in the in-cell fraction ds: g ~ c0 + c1*ds + c2*ds^2.
__device__ float4 d_lutq[LUTQ_N];

// ---------------- helpers ----------------
// XOR bits [1:4) with bits [4:7): conflict-free for both phases AND preserves
// bit0 -> adjacent even/odd entry PAIRS stay adjacent & 16B-aligned.
__device__ __forceinline__ int swz(int i) { return i ^ (((i >> 4) & 0x7) << 1); }

__device__ __forceinline__ ull pack2(float lo, float hi) {
    ull v;
    asm("mov.b64 %0, {%1, %2};" : "=l"(v) : "f"(lo), "f"(hi));
    return v;
}

__device__ __forceinline__ void unpack2(ull v, float& lo, float& hi) {
    asm("mov.b64 {%0, %1}, %2;" : "=f"(lo), "=f"(hi) : "l"(v));
}

__device__ __forceinline__ ull fma2(ull a, ull b, ull c) {
    ull d;
    asm("fma.rn.f32x2 %0, %1, %2, %3;" : "=l"(d) : "l"(a), "l"(b), "l"(c));
    return d;
}

// ------- LUT build: g(s) = OUT_SCALE * (sum_o w2[o]*tanh(w1[o]*sqrt(s))) / sqrt(s) -------
__global__ void build_lutq_kernel(const float* __restrict__ w1,
                                  const float* __restrict__ w2) {
    int i = blockIdx.x * blockDim.x + threadIdx.x;
    if (i >= LUTQ_N) return;

    float a[8], b[8];
#pragma unroll
    for (int o = 0; o < 8; o++) { a[o] = w1[o]; b[o] = w2[o]; }

    auto gf = [&](float s) -> float {
        if (s <= 0.0f) {
            float r = 0.0f;
#pragma unroll
            for (int o = 0; o < 8; o++) r += b[o] * a[o];   // lim tanh(w m)/m
            return OUT_SCALE * r;
        }
        float m = sqrtf(s);
        float r = 0.0f;
#pragma unroll
        for (int o = 0; o < 8; o++) r += b[o] * tanhf(a[o] * m);
        return OUT_SCALE * r / m;
    };

    const int   E  = i >> 4;
    const int   m4 = i & 15;
    const float p2 = (float)(1 << E);               // 2^E
    const float v0 = p2 * (1.0f + (float)m4 / 16.0f);
    const float h  = p2 / 16.0f;                    // cell width in v (== in s)
    const float s0 = v0 - 1.0f;

    float g0 = gf(s0);
    float gh = gf(s0 + 0.5f * h);
    float g1 = gf(s0 + h);
    // p(ds) = c0 + c1*ds + c2*ds^2 through (0,g0),(0.5,gh),(1,g1)
    float c2 = 2.0f * (g0 - 2.0f * gh + g1);
    float c1 = -3.0f * g0 + 4.0f * gh - g1;
    d_lutq[i] = make_float4(g0, c1, c2, 0.0f);
}

// ---------------- fused envelope-MLP + complex FIR ----------------
__global__ void __launch_bounds__(THREADS, 8)
fused_fir_kernel(const float* __restrict__ xr, const float* __restrict__ xi,
                 const float* __restrict__ kr, const float* __restrict__ ki,
                 float* __restrict__ out) {
    __shared__ float2 sg[SG_N];            // swizzled (gr, gi) pairs
    __shared__ ull    skq[FILTER_L * 2];   // per tap: [(kr,kr),(ki,ki)] 16B entry

    const int tid = threadIdx.x;
    const int row = blockIdx.y;
    const int w0  = blockIdx.x * TILE;

    if (tid < FILTER_L) {
        float a = kr[tid];
        float b = ki[tid];
        skq[2 * tid]     = pack2(a, a);
        skq[2 * tid + 1] = pack2(b, b);
    }

    const float* __restrict__ xrp = xr + (size_t)row * WIDTH + w0;
    const float* __restrict__ xip = xi + (size_t)row * WIDTH + w0;
    const int L = min(TILE + FILTER_L - 1, WIDTH - w0);  // valid inputs this tile

    // preprocess: float4 loads, v = 1 + mag^2 -> log-indexed quadratic LUT -> g
    for (int g4 = tid; g4 < NGROUPS; g4 += THREADS) {
        const int idx = g4 * 4;
        float ar[4], ai[4];
        if (idx + 3 < L) {
            float4 vr = *reinterpret_cast<const float4*>(xrp + idx);
            float4 vi = *reinterpret_cast<const float4*>(xip + idx);
            ar[0] = vr.x; ar[1] = vr.y; ar[2] = vr.z; ar[3] = vr.w;
            ai[0] = vi.x; ai[1] = vi.y; ai[2] = vi.z; ai[3] = vi.w;
        } else {
#pragma unroll
            for (int k = 0; k < 4; k++) {
                ar[k] = (idx + k < L) ? __ldg(xrp + idx + k) : 0.0f;
                ai[k] = (idx + k < L) ? __ldg(xip + idx + k) : 0.0f;
            }
        }
        float gv[4][2];
#pragma unroll
        for (int k = 0; k < 4; k++) {
            float a = ar[k], b = ai[k];
            float v = fmaf(a, a, fmaf(b, b, 1.0f));          // v = 1 + s >= 1
            unsigned bits = __float_as_uint(v);
            int ii = (int)(bits >> 19) - 2032;               // 16 cells/octave
            ii = min(ii, LUTQ_N - 1);                        // clamp huge s
            // in-cell fraction from low 19 mantissa bits (no cvt, no MUFU)
            float ds = __uint_as_float(((bits & 0x7FFFFu) << 4) | 0x3F800000u) - 1.0f;
            float4 c = __ldg(&d_lutq[ii]);
            float g  = fmaf(fmaf(c.z, ds, c.y), ds, c.x);
            gv[k][0] = g * a;
            gv[k][1] = g * b;
        }
        // entries (idx,idx+1) adjacent at swz(idx); (idx+2,idx+3) at swz(idx+2)
        *reinterpret_cast<float4*>(&sg[swz(idx)]) =
            make_float4(gv[0][0], gv[0][1], gv[1][0], gv[1][1]);
        *reinterpret_cast<float4*>(&sg[swz(idx + 2)]) =
            make_float4(gv[2][0], gv[2][1], gv[3][0], gv[3][1]);
    }
    __syncthreads();

    // FIR: RPT=8 consecutive outputs per thread via f32x2 FMAs.
    const int base = tid * RPT;

    ull acca[RPT], accb[RPT], Wn[RPT];
#pragma unroll
    for (int r = 0; r < RPT; r++) { acca[r] = 0ull; accb[r] = 0ull; }
#pragma unroll
    for (int p = 0; p < RPT / 2; p++) {
        ulonglong2 w = *reinterpret_cast<const ulonglong2*>(&sg[swz(base + 2 * p)]);
        Wn[2 * p]     = w.x;
        Wn[2 * p + 1] = w.y;
    }

#pragma unroll
    for (int t = 0; t < FILTER_L; t += 2) {
        ulonglong2 ka = *reinterpret_cast<const ulonglong2*>(&skq[2 * t]);
        ulonglong2 kb = *reinterpret_cast<const ulonglong2*>(&skq[2 * t + 2]);
        ulonglong2 wpair;
        ull wsingle;
        if (t < FILTER_L - 2)   // base+t+RPT is even -> valid 16B pair
            wpair = *reinterpret_cast<const ulonglong2*>(&sg[swz(base + t + RPT)]);
        else
            wsingle = *reinterpret_cast<const ull*>(&sg[swz(base + t + RPT)]);

#pragma unroll
        for (int r = 0; r < RPT; r++) {
            ull v = Wn[(t + r) & (RPT - 1)];
            acca[r] = fma2(v, ka.x, acca[r]);
            accb[r] = fma2(v, ka.y, accb[r]);
        }
        Wn[t & (RPT - 1)] = (t < FILTER_L - 2) ? wpair.x : wsingle;

#pragma unroll
        for (int r = 0; r < RPT; r++) {
            ull v = Wn[(t + 1 + r) & (RPT - 1)];
            acca[r] = fma2(v, kb.x, acca[r]);
            accb[r] = fma2(v, kb.y, accb[r]);
        }
        if (t < FILTER_L - 2)
            Wn[(t + 1) & (RPT - 1)] = wpair.y;
    }

    // epilogue: combine + store (STG.128 pairs when 16B-aligned)
    const size_t oelem = (size_t)row * WOUT + w0 + base;   // float2 index
    float2* op = reinterpret_cast<float2*>(out) + oelem;
    const int rem = WOUT - (w0 + base);   // may be <= 0 for tail threads

    float y[RPT][2];
#pragma unroll
    for (int r = 0; r < RPT; r++) {
        float ax, ay, bx, by;
        unpack2(acca[r], ax, ay);
        unpack2(accb[r], bx, by);
        y[r][0] = ax - by;
        y[r][1] = ay + bx;
    }

    if (rem >= RPT && ((oelem & 1) == 0)) {
        float4* op4 = reinterpret_cast<float4*>(op);
#pragma unroll
        for (int r = 0; r < RPT / 2; r++)
            op4[r] = make_float4(y[2 * r][0], y[2 * r][1],
                                 y[2 * r + 1][0], y[2 * r + 1][1]);
    } else {
#pragma unroll
        for (int r = 0; r < RPT; r++)
            if (r < rem) op[r] = make_float2(y[r][0], y[r][1]);
    }
}

extern "C" void kernel_launch(void* const* d_in, const int* in_sizes, int n_in,
                              void* d_out, int out_size) {
    const float* xr = (const float*)d_in[0];   // x_real  [16,64,16384,1]
    const float* xi = (const float*)d_in[1];   // x_imag
    const float* w1 = (const float*)d_in[2];   // w_nl1 [8]
    const float* w2 = (const float*)d_in[3];   // w_nl2 [8]
    const float* kr = (const float*)d_in[4];   // w_lin_real [32]
    const float* ki = (const float*)d_in[5];   // w_lin_imag [32]
    float* out = (float*)d_out;

    build_lutq_kernel<<<1, LUTQ_N>>>(w1, w2);

    dim3 grid((WOUT + TILE - 1) / TILE, NROWS);   // (16, 1024)
    fused_fir_kernel<<<grid, THREADS>>>(xr, xi, kr, ki, out);
}

// round 17
// speedup vs baseline: 1.6134x; 1.6134x over previous
#include <cuda_runtime.h>

typedef unsigned long long ull;

#define WIDTH     16384
#define WOUT      16353      // WIDTH - 32 + 1
#define NROWS     1024       // B*H = 16*64
#define FILTER_L  32
#define LUTQ_N    128        // 8 octaves x 16 cells, indexed by bits of v=1+s
#define TILE      1024
#define THREADS   128
#define RPT       8          // outputs per thread (TILE/THREADS)
#define SG_N      1056       // TILE + 31 halo, rounded to multiple of 16
#define NGROUPS   (SG_N/4)   // 264 float4-groups
#define OUT_SCALE 0.17782794100389226f  // sqrt(10^(-15/10))

// Entry i (i = 16*E + m4) covers v in [2^E*(1+m4/16), 2^E*(1+(m4+1)/16)),
// quadratic in the in-cell fraction ds: g ~ c0 + c1*ds + c2*ds^2.
__device__ float4 d_lutq[LUTQ_N];

// ---------------- helpers ----------------
// XOR bits [1:4) with bits [4:7): conflict-free for both phases AND preserves
// bit0 -> adjacent even/odd entry PAIRS stay adjacent & 16B-aligned.
__device__ __forceinline__ int swz(int i) { return i ^ (((i >> 4) & 0x7) << 1); }

__device__ __forceinline__ ull pack2(float lo, float hi) {
    ull v;
    asm("mov.b64 %0, {%1, %2};" : "=l"(v) : "f"(lo), "f"(hi));
    return v;
}

__device__ __forceinline__ void unpack2(ull v, float& lo, float& hi) {
    asm("mov.b64 {%0, %1}, %2;" : "=f"(lo), "=f"(hi) : "l"(v));
}

__device__ __forceinline__ ull fma2(ull a, ull b, ull c) {
    ull d;
    asm("fma.rn.f32x2 %0, %1, %2, %3;" : "=l"(d) : "l"(a), "l"(b), "l"(c));
    return d;
}

// ------- LUT build: g(s) = OUT_SCALE * (sum_o w2[o]*tanh(w1[o]*sqrt(s))) / sqrt(s) -------
__global__ void build_lutq_kernel(const float* __restrict__ w1,
                                  const float* __restrict__ w2) {
    int i = blockIdx.x * blockDim.x + threadIdx.x;
    if (i >= LUTQ_N) return;

    float a[8], b[8];
#pragma unroll
    for (int o = 0; o < 8; o++) { a[o] = w1[o]; b[o] = w2[o]; }

    auto gf = [&](float s) -> float {
        if (s <= 0.0f) {
            float r = 0.0f;
#pragma unroll
            for (int o = 0; o < 8; o++) r += b[o] * a[o];   // lim tanh(w m)/m
            return OUT_SCALE * r;
        }
        float m = sqrtf(s);
        float r = 0.0f;
#pragma unroll
        for (int o = 0; o < 8; o++) r += b[o] * tanhf(a[o] * m);
        return OUT_SCALE * r / m;
    };

    const int   E  = i >> 4;
    const int   m4 = i & 15;
    const float p2 = (float)(1 << E);               // 2^E
    const float v0 = p2 * (1.0f + (float)m4 / 16.0f);
    const float h  = p2 / 16.0f;                    // cell width in v (== in s)
    const float s0 = v0 - 1.0f;

    float g0 = gf(s0);
    float gh = gf(s0 + 0.5f * h);
    float g1 = gf(s0 + h);
    // p(ds) = c0 + c1*ds + c2*ds^2 through (0,g0),(0.5,gh),(1,g1)
    float c2 = 2.0f * (g0 - 2.0f * gh + g1);
    float c1 = -3.0f * g0 + 4.0f * gh - g1;
    d_lutq[i] = make_float4(g0, c1, c2, 0.0f);
}

// ---------------- fused envelope-MLP + complex FIR ----------------
__global__ void __launch_bounds__(THREADS, 8)
fused_fir_kernel(const float* __restrict__ xr, const float* __restrict__ xi,
                 const float* __restrict__ kr, const float* __restrict__ ki,
                 float* __restrict__ out) {
    __shared__ float4 slut[LUTQ_N];        // 2KB LUT copy (smem gather, no L1 camping)
    __shared__ float2 sg[SG_N];            // swizzled (gr, gi) pairs
    __shared__ ull    skq[FILTER_L * 2];   // per tap: [(kr,kr),(ki,ki)] 16B entry

    const int tid = threadIdx.x;
    const int row = blockIdx.y;
    const int w0  = blockIdx.x * TILE;

    if (tid < FILTER_L) {
        float a = kr[tid];
        float b = ki[tid];
        skq[2 * tid]     = pack2(a, a);
        skq[2 * tid + 1] = pack2(b, b);
    }
    slut[tid] = __ldg(&d_lutq[tid]);       // THREADS == LUTQ_N
    __syncthreads();

    const float* __restrict__ xrp = xr + (size_t)row * WIDTH + w0;
    const float* __restrict__ xip = xi + (size_t)row * WIDTH + w0;
    const int L = min(TILE + FILTER_L - 1, WIDTH - w0);  // valid inputs this tile

    // preprocess: float4 loads, v = 1 + mag^2 -> log-indexed quadratic LUT -> g
    for (int g4 = tid; g4 < NGROUPS; g4 += THREADS) {
        const int idx = g4 * 4;
        float ar[4], ai[4];
        if (idx + 3 < L) {
            float4 vr = *reinterpret_cast<const float4*>(xrp + idx);
            float4 vi = *reinterpret_cast<const float4*>(xip + idx);
            ar[0] = vr.x; ar[1] = vr.y; ar[2] = vr.z; ar[3] = vr.w;
            ai[0] = vi.x; ai[1] = vi.y; ai[2] = vi.z; ai[3] = vi.w;
        } else {
#pragma unroll
            for (int k = 0; k < 4; k++) {
                ar[k] = (idx + k < L) ? __ldg(xrp + idx + k) : 0.0f;
                ai[k] = (idx + k < L) ? __ldg(xip + idx + k) : 0.0f;
            }
        }
        float gv[4][2];
#pragma unroll
        for (int k = 0; k < 4; k++) {
            float a = ar[k], b = ai[k];
            float v = fmaf(a, a, fmaf(b, b, 1.0f));          // v = 1 + s >= 1
            unsigned bits = __float_as_uint(v);
            int ii = (int)(bits >> 19) - 2032;               // 16 cells/octave
            ii = min(ii, LUTQ_N - 1);                        // clamp huge s
            // in-cell fraction from low 19 mantissa bits (no cvt, no MUFU)
            float ds = __uint_as_float(((bits & 0x7FFFFu) << 4) | 0x3F800000u) - 1.0f;
            float4 c = slut[ii];
            float g  = fmaf(fmaf(c.z, ds, c.y), ds, c.x);
            gv[k][0] = g * a;
            gv[k][1] = g * b;
        }
        // entries (idx,idx+1) adjacent at swz(idx); (idx+2,idx+3) at swz(idx+2)
        *reinterpret_cast<float4*>(&sg[swz(idx)]) =
            make_float4(gv[0][0], gv[0][1], gv[1][0], gv[1][1]);
        *reinterpret_cast<float4*>(&sg[swz(idx + 2)]) =
            make_float4(gv[2][0], gv[2][1], gv[3][0], gv[3][1]);
    }
    __syncthreads();

    // FIR: RPT=8 consecutive outputs per thread via f32x2 FMAs.
    const int base = tid * RPT;

    ull acca[RPT], accb[RPT], Wn[RPT];
#pragma unroll
    for (int r = 0; r < RPT; r++) { acca[r] = 0ull; accb[r] = 0ull; }
#pragma unroll
    for (int p = 0; p < RPT / 2; p++) {
        ulonglong2 w = *reinterpret_cast<const ulonglong2*>(&sg[swz(base + 2 * p)]);
        Wn[2 * p]     = w.x;
        Wn[2 * p + 1] = w.y;
    }

#pragma unroll
    for (int t = 0; t < FILTER_L; t += 2) {
        ulonglong2 ka = *reinterpret_cast<const ulonglong2*>(&skq[2 * t]);
        ulonglong2 kb = *reinterpret_cast<const ulonglong2*>(&skq[2 * t + 2]);
        ulonglong2 wpair;
        ull wsingle;
        if (t < FILTER_L - 2)   // base+t+RPT is even -> valid 16B pair
            wpair = *reinterpret_cast<const ulonglong2*>(&sg[swz(base + t + RPT)]);
        else
            wsingle = *reinterpret_cast<const ull*>(&sg[swz(base + t + RPT)]);

#pragma unroll
        for (int r = 0; r < RPT; r++) {
            ull v = Wn[(t + r) & (RPT - 1)];
            acca[r] = fma2(v, ka.x, acca[r]);
            accb[r] = fma2(v, ka.y, accb[r]);
        }
        Wn[t & (RPT - 1)] = (t < FILTER_L - 2) ? wpair.x : wsingle;

#pragma unroll
        for (int r = 0; r < RPT; r++) {
            ull v = Wn[(t + 1 + r) & (RPT - 1)];
            acca[r] = fma2(v, kb.x, acca[r]);
            accb[r] = fma2(v, kb.y, accb[r]);
        }
        if (t < FILTER_L - 2)
            Wn[(t + 1) & (RPT - 1)] = wpair.y;
    }

    // epilogue: combine + store (STG.128 pairs when 16B-aligned)
    const size_t oelem = (size_t)row * WOUT + w0 + base;   // float2 index
    float2* op = reinterpret_cast<float2*>(out) + oelem;
    const int rem = WOUT - (w0 + base);   // may be <= 0 for tail threads

    float y[RPT][2];
#pragma unroll
    for (int r = 0; r < RPT; r++) {
        float ax, ay, bx, by;
        unpack2(acca[r], ax, ay);
        unpack2(accb[r], bx, by);
        y[r][0] = ax - by;
        y[r][1] = ay + bx;
    }

    if (rem >= RPT && ((oelem & 1) == 0)) {
        float4* op4 = reinterpret_cast<float4*>(op);
#pragma unroll
        for (int r = 0; r < RPT / 2; r++)
            op4[r] = make_float4(y[2 * r][0], y[2 * r][1],
                                 y[2 * r + 1][0], y[2 * r + 1][1]);
    } else {
#pragma unroll
        for (int r = 0; r < RPT; r++)
            if (r < rem) op[r] = make_float2(y[r][0], y[r][1]);
    }
}

extern "C" void kernel_launch(void* const* d_in, const int* in_sizes, int n_in,
                              void* d_out, int out_size) {
    const float* xr = (const float*)d_in[0];   // x_real  [16,64,16384,1]
    const float* xi = (const float*)d_in[1];   // x_imag
    const float* w1 = (const float*)d_in[2];   // w_nl1 [8]
    const float* w2 = (const float*)d_in[3];   // w_nl2 [8]
    const float* kr = (const float*)d_in[4];   // w_lin_real [32]
    const float* ki = (const float*)d_in[5];   // w_lin_imag [32]
    float* out = (float*)d_out;

    build_lutq_kernel<<<1, LUTQ_N>>>(w1, w2);

    dim3 grid((WOUT + TILE - 1) / TILE, NROWS);   // (16, 1024)
    fused_fir_kernel<<<grid, THREADS>>>(xr, xi, kr, ki, out);
}